// round 12
// baseline (speedup 1.0000x reference)
#include <cuda_runtime.h>
#include <cuda_bf16.h>
#include <math.h>

// ---------------- Problem constants ----------------
#define BB   32
#define TT   1024
#define EE   256
#define HDD  256          // hidden per direction
#define G4   1024         // 4*HD
#define KK   48
#define NEGV (-10000.0f)

// ---------------- Device scratch (static; no allocs allowed) ----------------
__device__ float d_G[2ull * TT * G4 * BB];       // [dir][t][gate_row][b]
__device__ float d_hs[2ull * TT * HDD * BB];     // [dir][t][unit][b]
__device__ float d_feats[(size_t)BB * TT * KK];  // [b][t][k]
__device__ int   d_bar[64];                      // spin barrier counters (dir*32)

// =====================================================================
// Kernel 0: reset barrier counters (fresh for every graph replay)
// =====================================================================
__global__ void k_reset() {
    if (threadIdx.x < 64) d_bar[threadIdx.x] = 0;
}

// =====================================================================
// Kernel 1: fused embedding-gather + input GEMM (+ bih + bhh)
// G[d][t][r][b] = sum_e emb[sent[b][t]][e] * Wih_d[r][e] + bih_d[r] + bhh_d[r]
// M = 32768 tokens (token = t*32+b), N = 2048 (2 dirs x 1024), K = 256
// CTA tile 64x64, 256 threads, 4x4 microtile, K-chunk 16.
// =====================================================================
__global__ void __launch_bounds__(256) k_gemm_in(
    const int*   __restrict__ sent,
    const float* __restrict__ emb,
    const float* __restrict__ Wf,  const float* __restrict__ Wb,
    const float* __restrict__ bif, const float* __restrict__ bhf,
    const float* __restrict__ bib, const float* __restrict__ bhb)
{
    __shared__ __align__(16) float aT[16][68];
    __shared__ __align__(16) float wT[16][68];
    __shared__ int tok[64];

    int tid = threadIdx.x;
    int mt  = blockIdx.x;            // 0..511  token tiles of 64 (= 2 t's x 32 b)
    int nt  = blockIdx.y;            // 0..31   row tiles of 64
    int d   = nt >> 4;
    int rbase = (nt & 15) * 64;
    const float* W = d ? Wb : Wf;

    if (tid < 64) {
        int token = mt * 64 + tid;
        int t = token >> 5, b = token & 31;
        tok[tid] = sent[b * TT + t];
    }
    __syncthreads();

    float acc[4][4];
#pragma unroll
    for (int i = 0; i < 4; ++i)
#pragma unroll
        for (int j = 0; j < 4; ++j) acc[i][j] = 0.f;

    int lm = tid >> 2;            // 0..63  load row (m or n index)
    int kq = (tid & 3) * 4;       // 0,4,8,12
    int mx = tid & 15;            // compute grid 16 x 16
    int nx = tid >> 4;

    for (int kc = 0; kc < EE; kc += 16) {
        float4 av = *(const float4*)&emb[(size_t)tok[lm] * EE + kc + kq];
        float4 wv = *(const float4*)&W[(size_t)(rbase + lm) * EE + kc + kq];
        __syncthreads();
        aT[kq + 0][lm] = av.x; aT[kq + 1][lm] = av.y;
        aT[kq + 2][lm] = av.z; aT[kq + 3][lm] = av.w;
        wT[kq + 0][lm] = wv.x; wT[kq + 1][lm] = wv.y;
        wT[kq + 2][lm] = wv.z; wT[kq + 3][lm] = wv.w;
        __syncthreads();
#pragma unroll
        for (int k = 0; k < 16; ++k) {
            float4 a4 = *(const float4*)&aT[k][mx * 4];
            float4 w4 = *(const float4*)&wT[k][nx * 4];
            float aa[4] = {a4.x, a4.y, a4.z, a4.w};
            float ww[4] = {w4.x, w4.y, w4.z, w4.w};
#pragma unroll
            for (int ni = 0; ni < 4; ++ni)
#pragma unroll
                for (int mi = 0; mi < 4; ++mi)
                    acc[ni][mi] += ww[ni] * aa[mi];
        }
    }

    const float* bi = d ? bib : bif;
    const float* bh = d ? bhb : bhf;
    int token0 = mt * 64 + mx * 4;     // 4 consecutive tokens share t
    int t  = token0 >> 5;
    int b0 = token0 & 31;
#pragma unroll
    for (int ni = 0; ni < 4; ++ni) {
        int r = rbase + nx * 4 + ni;
        float bias = bi[r] + bh[r];
        float4 o;
        o.x = acc[ni][0] + bias; o.y = acc[ni][1] + bias;
        o.z = acc[ni][2] + bias; o.w = acc[ni][3] + bias;
        *(float4*)&d_G[(((size_t)d * TT + t) * G4 + r) * BB + b0] = o;
    }
}

// =====================================================================
// Kernel 2: persistent bidirectional LSTM recurrence
// grid = 128 CTAs: [0,64) forward, [64,128) backward. CTA owns 4 hidden
// units (16 gate rows) x 32 batches. 8 warps = 8 k-slices of 32, lane=batch.
// Whh slice in smem (loaded once), weights via broadcast LDS.128,
// smem partial-sum reduce, per-direction global spin barrier per step.
// =====================================================================
__device__ __forceinline__ float sigf(float x) { return 1.0f / (1.0f + expf(-x)); }

__global__ void __launch_bounds__(256, 1) k_lstm(
    const float* __restrict__ Whf, const float* __restrict__ Whb)
{
    __shared__ __align__(16) float w_sm[16][256];  // 16 KB, local row r = g*4+ui
    __shared__ float ps[8][16][32];                // 16 KB partials
    __shared__ float red[16][32];                  //  2 KB reduced gates

    int tid  = threadIdx.x;
    int lane = tid & 31;                           // batch
    int wid  = tid >> 5;                           // k-slice / warp id
    int dir  = blockIdx.x >> 6;
    int u0   = (blockIdx.x & 63) * 4;
    const float* Wh = dir ? Whb : Whf;

    // load Whh slice: local row r = g*4+ui -> global row g*256 + u0 + ui
    for (int idx = tid; idx < 16 * 256; idx += 256) {
        int r = idx >> 8, k = idx & 255;
        int grow = (r >> 2) * HDD + u0 + (r & 3);
        w_sm[r][k] = Wh[(size_t)grow * HDD + k];
    }
    __syncthreads();

    float c = 0.f;
    int ui = wid & 3;                               // valid when tid < 128
    size_t gbase = (size_t)dir * TT * G4 * BB;
    size_t hbase = (size_t)dir * TT * HDD * BB;
    int* barp = &d_bar[dir * 32];
    volatile int* barv = (volatile int*)barp;

    for (int s = 0; s < TT; ++s) {
        int t = dir ? (TT - 1 - s) : s;

        // input-gate contributions: independent of barrier, load early
        float gin[4];
        if (tid < 128) {
#pragma unroll
            for (int g = 0; g < 4; ++g)
                gin[g] = d_G[gbase + ((size_t)t * G4 + g * HDD + u0 + ui) * BB + lane];
        }

        if (s > 0) {
            int target = s << 6;                    // 64*s arrivals
            if (tid == 0) { while (*barv < target) {} }
            __syncthreads();
        }

        float acc[16];
#pragma unroll
        for (int r = 0; r < 16; ++r) acc[r] = 0.f;

        if (s > 0) {
            int tp = dir ? (t + 1) : (t - 1);
            const float* hp = &d_hs[hbase + ((size_t)tp * HDD + wid * 32) * BB + lane];
            float h_reg[32];
#pragma unroll
            for (int i = 0; i < 32; ++i) h_reg[i] = hp[(size_t)i * 32];
#pragma unroll
            for (int r = 0; r < 16; ++r) {
#pragma unroll
                for (int i4 = 0; i4 < 8; ++i4) {
                    float4 w4 = *(const float4*)&w_sm[r][wid * 32 + i4 * 4];
                    acc[r] += w4.x * h_reg[i4 * 4 + 0];
                    acc[r] += w4.y * h_reg[i4 * 4 + 1];
                    acc[r] += w4.z * h_reg[i4 * 4 + 2];
                    acc[r] += w4.w * h_reg[i4 * 4 + 3];
                }
            }
        }

#pragma unroll
        for (int r = 0; r < 16; ++r) ps[wid][r][lane] = acc[r];
        __syncthreads();

        // reduce 8 warp-partials: 512 outputs over 256 threads (2 each)
        {
            int o1 = tid, o2 = tid + 256;
            float s1 = 0.f, s2 = 0.f;
#pragma unroll
            for (int w = 0; w < 8; ++w) {
                s1 += ps[w][o1 >> 5][o1 & 31];
                s2 += ps[w][o2 >> 5][o2 & 31];
            }
            red[o1 >> 5][o1 & 31] = s1;
            red[o2 >> 5][o2 & 31] = s2;
        }
        __syncthreads();

        // cell update: tid<128 -> (unit u0+ui, batch=lane)
        if (tid < 128) {
            float gi = gin[0] + red[0 * 4 + ui][lane];
            float gf = gin[1] + red[1 * 4 + ui][lane];
            float gg = gin[2] + red[2 * 4 + ui][lane];
            float go = gin[3] + red[3 * 4 + ui][lane];
            c = sigf(gf) * c + sigf(gi) * tanhf(gg);
            float h = sigf(go) * tanhf(c);
            d_hs[hbase + ((size_t)t * HDD + u0 + ui) * BB + lane] = h;
            __threadfence();
        }
        __syncthreads();
        if (tid == 0) atomicAdd(barp, 1);
    }
}

// =====================================================================
// Kernel 3: feats GEMM  feats[b][t][k] = concat(hf,hb)[b][t][:] . W_out[k][:] + b_out[k]
// grid = 1024 (one CTA per t), 256 threads. K-dim 512 in 4 chunks of 128.
// =====================================================================
__global__ void __launch_bounds__(256) k_feats(
    const float* __restrict__ Wout, const float* __restrict__ bout)
{
    __shared__ __align__(16) float hsm[32][132];   // [b][i], padded
    __shared__ __align__(16) float wsm[48][128];   // [k][i]

    int tid = threadIdx.x;
    int t   = blockIdx.x;
    int b   = tid & 31;
    int kw  = tid >> 5;                            // warp id 0..7; k = kw + 8p

    float acc[6];
#pragma unroll
    for (int p = 0; p < 6; ++p) acc[p] = 0.f;

    for (int cck = 0; cck < 4; ++cck) {
        // stage h chunk: units uu = cck*128 + i (hf then hb)
        for (int idx = tid; idx < 128 * 32; idx += 256) {
            int i = idx >> 5, b2 = idx & 31;
            int uu = cck * 128 + i;
            int dd = uu >> 8;
            int u  = uu & 255;
            hsm[b2][i] = d_hs[(((size_t)dd * TT + t) * HDD + u) * BB + b2];
        }
        // stage W chunk
        for (int idx = tid; idx < 48 * 128; idx += 256) {
            int k = idx >> 7, i = idx & 127;
            wsm[k][i] = Wout[(size_t)k * 512 + cck * 128 + i];
        }
        __syncthreads();

#pragma unroll 4
        for (int i4 = 0; i4 < 32; ++i4) {
            float4 h4 = *(const float4*)&hsm[b][i4 * 4];
#pragma unroll
            for (int p = 0; p < 6; ++p) {
                float4 w4 = *(const float4*)&wsm[kw + 8 * p][i4 * 4];
                acc[p] += w4.x * h4.x + w4.y * h4.y + w4.z * h4.z + w4.w * h4.w;
            }
        }
        __syncthreads();
    }

#pragma unroll
    for (int p = 0; p < 6; ++p) {
        int k = kw + 8 * p;
        d_feats[((size_t)b * TT + t) * KK + k] = acc[p] + bout[k];
    }
}

// =====================================================================
// Kernel 4: Viterbi per batch. 32 CTAs x 64 threads.
// Dynamic smem: trans padded [48][49] + backpointers u8[1024][48] + fv x2 + tags
// =====================================================================
#define VIT_TRP   (48 * 49 * 4)                    // 9408
#define VIT_BPTR  (1024 * 48)                      // 49152
#define VIT_FV    (2 * 48 * 4)                     // 384
#define VIT_TAGS  (1024 * 4)                       // 4096
#define VIT_SMEM  (VIT_TRP + VIT_BPTR + VIT_FV + VIT_TAGS)

__global__ void __launch_bounds__(64) k_viterbi(
    const float* __restrict__ trans, float* __restrict__ out)
{
    extern __shared__ char sm[];
    float*         trp  = (float*)sm;                                  // [48][49]
    unsigned char* bptr = (unsigned char*)(sm + VIT_TRP);              // [1024][48]
    float*         fvA  = (float*)(sm + VIT_TRP + VIT_BPTR);
    float*         fvB  = fvA + 48;
    int*           tags = (int*)(sm + VIT_TRP + VIT_BPTR + VIT_FV);
    __shared__ float redsm[64];

    int b = blockIdx.x, tid = threadIdx.x;
    const float* fb = d_feats + (size_t)b * TT * KK;

    for (int idx = tid; idx < 48 * 48; idx += 64)
        trp[(idx / 48) * 49 + (idx % 48)] = trans[idx];
    if (tid < 48) fvA[tid] = (tid == 47) ? 0.f : NEGV;
    __syncthreads();

    float* fv  = fvA;
    float* fvn = fvB;
    for (int t = 0; t < TT; ++t) {
        if (tid < 48) {
            float ft = fb[t * KK + tid];
            float m = -1e30f; int arg = 0;
#pragma unroll 8
            for (int j = 0; j < 48; ++j) {
                float v = fv[j] + trp[tid * 49 + j];
                if (v > m) { m = v; arg = j; }     // strict > keeps FIRST max (jnp.argmax)
            }
            fvn[tid] = m + ft;
            bptr[t * 48 + tid] = (unsigned char)arg;
        }
        __syncthreads();
        float* tmp = fv; fv = fvn; fvn = tmp;
    }

    // backtrack (sequential, smem-resident)
    if (tid == 0) {
        float m = -1e30f; int last = 0;
        for (int j = 0; j < 48; ++j)
            if (fv[j] > m) { m = fv[j]; last = j; }
        tags[TT - 1] = last;
        int cur = last;
        for (int t = TT - 2; t >= 0; --t) {
            cur = bptr[(t + 1) * 48 + cur];
            tags[t] = cur;
        }
    }
    __syncthreads();

    // emit tags (as floats, reference tuple order: score[32] then tags[32][1024])
    for (int t = tid; t < TT; t += 64)
        out[32 + b * TT + t] = (float)tags[t];

    // score = feats[b][T-1][tags[0]]
    //       + sum_{t=0..T-2} trans[tags[t]][tags[t+1]]
    //       + sum_{t=1..T-1} feats[b][t][tags[t]]
    float s = 0.f;
    for (int t = tid; t < TT - 1; t += 64)
        s += trp[tags[t] * 49 + tags[t + 1]];
    for (int t = tid; t < TT; t += 64)
        if (t >= 1) s += fb[t * KK + tags[t]];
    redsm[tid] = s;
    __syncthreads();
    if (tid == 0) {
        float tot = fb[(TT - 1) * KK + tags[0]];
        for (int i = 0; i < 64; ++i) tot += redsm[i];
        out[b] = tot;
    }
}

// =====================================================================
extern "C" void kernel_launch(void* const* d_in, const int* in_sizes, int n_in,
                              void* d_out, int out_size)
{
    const int*   sent  = (const int*)  d_in[0];
    const float* emb   = (const float*)d_in[1];
    const float* Wih_f = (const float*)d_in[2];
    const float* Whh_f = (const float*)d_in[3];
    const float* bih_f = (const float*)d_in[4];
    const float* bhh_f = (const float*)d_in[5];
    const float* Wih_b = (const float*)d_in[6];
    const float* Whh_b = (const float*)d_in[7];
    const float* bih_b = (const float*)d_in[8];
    const float* bhh_b = (const float*)d_in[9];
    const float* W_out = (const float*)d_in[10];
    const float* b_out = (const float*)d_in[11];
    const float* trans = (const float*)d_in[12];
    float* out = (float*)d_out;

    cudaFuncSetAttribute(k_viterbi, cudaFuncAttributeMaxDynamicSharedMemorySize, 65536);

    k_reset<<<1, 64>>>();

    dim3 g1(512, 32);
    k_gemm_in<<<g1, 256>>>(sent, emb, Wih_f, Wih_b, bih_f, bhh_f, bih_b, bhh_b);

    k_lstm<<<128, 256>>>(Whh_f, Whh_b);

    k_feats<<<TT, 256>>>(W_out, b_out);

    k_viterbi<<<BB, 64, VIT_SMEM>>>(trans, out);
}